// round 2
// baseline (speedup 1.0000x reference)
#include <cuda_runtime.h>
#include <math.h>

// Problem constants (fixed by setup_inputs)
#define B   32
#define S   128
#define I_DIM 1024
#define H   1024
#define G   4096      // 4*H
#define V   32000

// ---------------------------------------------------------------------------
// Scratch (static __device__ arrays; no allocation allowed)
// ---------------------------------------------------------------------------
__device__ float d_xg[(size_t)S * B * G];       // 67 MB: precomputed input gates (S,B,4H)
__device__ float d_hbuf[2][B * H];              // ping-pong hidden state
__device__ float d_cbuf[B * H];                 // cell state
__device__ float d_hs[(size_t)B * (S) * H];     // stored h for s>=ctx, layout (b, s', H) (oversized, safe)
__device__ int   d_rowids[S * B];               // gather indices for embed GEMM

// ---------------------------------------------------------------------------
// Init: zero h0/c, build gather row ids.  m = s*B + b  ->  ids[b*S + s]
// ---------------------------------------------------------------------------
__global__ void init_kernel(const int* __restrict__ ids, int* __restrict__ rowids,
                            float* __restrict__ h0, float* __restrict__ c)
{
    int t = blockIdx.x * blockDim.x + threadIdx.x;
    if (t < S * B) {
        int s = t >> 5;         // t / 32
        int b = t & 31;
        rowids[t] = ids[b * S + s];
    }
    if (t < B * H) {
        h0[t] = 0.f;
        c[t]  = 0.f;
    }
}

// ---------------------------------------------------------------------------
// Generic fp32 GEMM:  C[m][n] = sum_k A[row(m)][k] * Bm[n][k] (+bias1[n]+bias2[n])
// A is (M,K) row-major (optionally gathered via arow), Bm is (N,K) row-major.
// 64x64 tile, BK=16, 256 threads, 4x4 per thread.
// Requires M%64==0, N%64==0, K%16==0 (true for all our shapes).
// ---------------------------------------------------------------------------
#define BM 64
#define BN 64
#define BKK 16

__global__ __launch_bounds__(256, 2)
void gemm_nt(const float* __restrict__ A, const float* __restrict__ Bm,
             const float* __restrict__ bias1, const float* __restrict__ bias2,
             float* __restrict__ C,
             int M, int N, int K,
             const int* __restrict__ arow)
{
    __shared__ float As[BKK][BM + 1];
    __shared__ float Bs[BKK][BN + 1];

    const int bm = blockIdx.y * BM;
    const int bn = blockIdx.x * BN;
    const int t  = threadIdx.x;
    const int tx = t & 15;   // n-sub (0..15)
    const int ty = t >> 4;   // m-sub (0..15)

    const int lrow = t >> 2;        // 0..63 (load row)
    const int lkq  = (t & 3) * 4;   // 0,4,8,12

    // Resolve the (possibly gathered) A row pointer once
    long arowIdx = arow ? (long)arow[bm + lrow] : (long)(bm + lrow);
    const float* Ap = A + arowIdx * K + lkq;
    const float* Bp = Bm + (long)(bn + lrow) * K + lkq;

    float acc[4][4];
    #pragma unroll
    for (int i = 0; i < 4; i++)
        #pragma unroll
        for (int j = 0; j < 4; j++) acc[i][j] = 0.f;

    for (int k0 = 0; k0 < K; k0 += BKK) {
        float4 va = *(const float4*)(Ap + k0);
        float4 vb = *(const float4*)(Bp + k0);
        As[lkq + 0][lrow] = va.x; As[lkq + 1][lrow] = va.y;
        As[lkq + 2][lrow] = va.z; As[lkq + 3][lrow] = va.w;
        Bs[lkq + 0][lrow] = vb.x; Bs[lkq + 1][lrow] = vb.y;
        Bs[lkq + 2][lrow] = vb.z; Bs[lkq + 3][lrow] = vb.w;
        __syncthreads();

        #pragma unroll
        for (int k = 0; k < BKK; k++) {
            float a[4], b[4];
            #pragma unroll
            for (int i = 0; i < 4; i++) a[i] = As[k][ty * 4 + i];
            #pragma unroll
            for (int j = 0; j < 4; j++) b[j] = Bs[k][tx * 4 + j];
            #pragma unroll
            for (int i = 0; i < 4; i++)
                #pragma unroll
                for (int j = 0; j < 4; j++) acc[i][j] += a[i] * b[j];
        }
        __syncthreads();
    }

    #pragma unroll
    for (int i = 0; i < 4; i++) {
        int m = bm + ty * 4 + i;
        #pragma unroll
        for (int j = 0; j < 4; j++) {
            int n = bn + tx * 4 + j;
            float v = acc[i][j];
            if (bias1) v += bias1[n];
            if (bias2) v += bias2[n];
            C[(long)m * N + n] = v;
        }
    }
}

// ---------------------------------------------------------------------------
// LSTM step: gates(32 x 4096) = xg[s] + h_in @ w_hh^T, then pointwise update.
// Each block owns 8 h-columns (n0..n0+7); computes the 4 gate columns
// {n, H+n, 2H+n, 3H+n} per h-column so the pointwise stage is in-register.
// grid = 128 blocks, 256 threads (thread = (b in 0..31, j in 0..7)).
// ---------------------------------------------------------------------------
#define KT 128

__global__ __launch_bounds__(256, 2)
void lstm_step(const float* __restrict__ xg,    // + s*B*G
               const float* __restrict__ w_hh,  // (4096,1024)
               const float* __restrict__ h_in,
               float* __restrict__ h_out,
               float* __restrict__ c,
               float* __restrict__ hs,          // base of (b, s', H) buffer
               int store_off,                   // s-ctx, or -1
               int Sact)
{
    __shared__ float sh[KT][33];   // h chunk, [k][b]
    __shared__ float sw[KT][33];   // w chunk, [k][r], r = gate*8 + j

    const int t  = threadIdx.x;
    const int b  = t & 31;
    const int j  = t >> 5;          // 0..7
    const int n0 = blockIdx.x * 8;

    float acc0 = 0.f, acc1 = 0.f, acc2 = 0.f, acc3 = 0.f;

    for (int k0 = 0; k0 < H; k0 += KT) {
        #pragma unroll
        for (int i = 0; i < 16; i++) {
            int idx = t + 256 * i;          // 0..4095
            int rr  = idx >> 7;             // 0..31
            int kk  = idx & 127;
            sh[kk][rr] = h_in[rr * H + k0 + kk];
            int gate = rr >> 3;
            int jj   = rr & 7;
            sw[kk][rr] = w_hh[(long)(gate * H + n0 + jj) * H + k0 + kk];
        }
        __syncthreads();

        #pragma unroll 8
        for (int k = 0; k < KT; k++) {
            float hv = sh[k][b];
            acc0 += hv * sw[k][j];
            acc1 += hv * sw[k][8 + j];
            acc2 += hv * sw[k][16 + j];
            acc3 += hv * sw[k][24 + j];
        }
        __syncthreads();
    }

    const int n = n0 + j;
    float gi = acc0 + xg[b * G + n];
    float gf = acc1 + xg[b * G + H + n];
    float gg = acc2 + xg[b * G + 2 * H + n];
    float go = acc3 + xg[b * G + 3 * H + n];

    float iv = 1.f / (1.f + expf(-gi));
    float fv = 1.f / (1.f + expf(-gf));
    float gv = tanhf(gg);
    float ov = 1.f / (1.f + expf(-go));

    int cidx = b * H + n;
    float cv = fv * c[cidx] + iv * gv;
    c[cidx] = cv;
    float hv = ov * tanhf(cv);
    h_out[cidx] = hv;

    if (store_off >= 0)
        hs[((long)b * Sact + store_off) * H + n] = hv;
}

// ---------------------------------------------------------------------------
// Launch
// ---------------------------------------------------------------------------
extern "C" void kernel_launch(void* const* d_in, const int* in_sizes, int n_in,
                              void* d_out, int out_size)
{
    const int*   ids   = (const int*)  d_in[0];
    const float* emb   = (const float*)d_in[1];
    const float* w_ih  = (const float*)d_in[2];
    const float* w_hh  = (const float*)d_in[3];
    const float* b_ih  = (const float*)d_in[4];
    const float* b_hh  = (const float*)d_in[5];
    const float* w_out = (const float*)d_in[6];
    const float* b_out = (const float*)d_in[7];

    // context_seq derived from output size (out = B*(S-ctx)*V elements)
    int ctx  = S - (int)((long)out_size / ((long)B * V));   // = 40
    int Sact = S - ctx;                                     // = 88

    float* xg;     cudaGetSymbolAddress((void**)&xg,     d_xg);
    float* hbuf;   cudaGetSymbolAddress((void**)&hbuf,   d_hbuf);
    float* cbuf;   cudaGetSymbolAddress((void**)&cbuf,   d_cbuf);
    float* hs;     cudaGetSymbolAddress((void**)&hs,     d_hs);
    int*   rowids; cudaGetSymbolAddress((void**)&rowids, d_rowids);

    // 1) init h0/c, gather indices
    init_kernel<<<(B * H + 255) / 256, 256>>>(ids, rowids, hbuf, cbuf);

    // 2) x_gates = gather(emb, ids) @ w_ih^T + b_ih + b_hh     (4096 x 4096 x 1024)
    gemm_nt<<<dim3(G / BN, (S * B) / BM), 256>>>(
        emb, w_ih, b_ih, b_hh, xg, S * B, G, I_DIM, rowids);

    // 3) sequential scan
    for (int s = 0; s < S; s++) {
        const float* h_in = hbuf + (size_t)(s & 1) * (B * H);
        float* h_out      = hbuf + (size_t)((s + 1) & 1) * (B * H);
        lstm_step<<<H / 8, 256>>>(
            xg + (size_t)s * B * G, w_hh, h_in, h_out, cbuf, hs,
            (s >= ctx) ? (s - ctx) : -1, Sact);
    }

    // 4) logits = hs_flat @ w_out^T + b_out    (2816 x 32000 x 1024)
    gemm_nt<<<dim3(V / BN, (B * Sact) / BM), 256>>>(
        hs, w_out, b_out, nullptr, (float*)d_out, B * Sact, V, H, nullptr);
}

// round 4
// speedup vs baseline: 2.4490x; 2.4490x over previous
#include <cuda_runtime.h>
#include <math.h>

// Problem constants (fixed by setup_inputs)
#define B   32
#define S   128
#define I_DIM 1024
#define H   1024
#define G   4096      // 4*H
#define V   32000

// ---------------------------------------------------------------------------
// Scratch (static __device__ arrays; no allocation allowed)
// ---------------------------------------------------------------------------
__device__ float d_xg[(size_t)S * B * G];       // 67 MB: precomputed input gates (S,B,4H)
__device__ float d_hbuf[2][B * H];              // ping-pong hidden state
__device__ float d_cbuf[B * H];                 // cell state
__device__ float d_hs[(size_t)B * S * H];       // stored h for s>=ctx, layout (b, s', H)
__device__ int   d_rowids[S * B];               // gather indices for embed GEMM

// ---------------------------------------------------------------------------
// Init: zero h0/c, build gather row ids.  m = s*B + b  ->  ids[b*S + s]
// ---------------------------------------------------------------------------
__global__ void init_kernel(const int* __restrict__ ids, int* __restrict__ rowids,
                            float* __restrict__ h0, float* __restrict__ c)
{
    int t = blockIdx.x * blockDim.x + threadIdx.x;
    if (t < S * B) {
        int s = t >> 5;
        int b = t & 31;
        rowids[t] = ids[b * S + s];
    }
    if (t < B * H) {
        h0[t] = 0.f;
        c[t]  = 0.f;
    }
}

// ---------------------------------------------------------------------------
// tf32 helpers
// ---------------------------------------------------------------------------
__device__ __forceinline__ unsigned f2tf(float f) {
    unsigned r;
    asm("cvt.rna.tf32.f32 %0, %1;" : "=r"(r) : "f"(f));
    return r;
}

#define MMA_TF32(d, a, b)                                                     \
    asm volatile(                                                             \
        "mma.sync.aligned.m16n8k8.row.col.f32.tf32.tf32.f32 "                 \
        "{%0,%1,%2,%3}, {%4,%5,%6,%7}, {%8,%9}, {%0,%1,%2,%3};\n"             \
        : "+f"(d[0]), "+f"(d[1]), "+f"(d[2]), "+f"(d[3])                      \
        : "r"(a[0]), "r"(a[1]), "r"(a[2]), "r"(a[3]), "r"(b[0]), "r"(b[1]))

// ---------------------------------------------------------------------------
// tf32 tensor-core GEMM:  C[m][n] = A[row(m)][:] . Bm[n][:]  (+bias1[n]+bias2[n])
// A (M,K) row-major (optional row gather via arow), Bm (N,K) row-major.
// BM=BN=128, BK=16, 256 threads (8 warps = 2m x 4n), warp tile 64x32,
// mma.m16n8k8 grid 4x4 per warp.  Requires M%128==0, N%128==0, K%16==0.
// ---------------------------------------------------------------------------
__global__ __launch_bounds__(256)
void gemm_tf32(const float* __restrict__ A, const float* __restrict__ Bm,
               const float* __restrict__ bias1, const float* __restrict__ bias2,
               float* __restrict__ C,
               int M, int N, int K,
               const int* __restrict__ arow)
{
    __shared__ unsigned As[128][20];   // pad 20: conflict-free frag loads
    __shared__ unsigned Bs[128][20];

    const int bm = blockIdx.y * 128;
    const int bn = blockIdx.x * 128;
    const int t    = threadIdx.x;
    const int lane = t & 31;
    const int w    = t >> 5;
    const int wm   = (w >> 2) * 64;   // warp m offset (0 or 64)
    const int wn   = (w & 3) * 32;    // warp n offset (0..96)
    const int gid  = lane >> 2;       // 0..7
    const int tk   = lane & 3;        // 0..3

    // Tile-load mapping: thread covers rows r0 and r0+64, one float4 (4 k) each.
    const int r0 = t >> 2;            // 0..63
    const int r1 = r0 + 64;
    const int kq = (t & 3) * 4;       // 0,4,8,12

    long ar0 = arow ? (long)arow[bm + r0] : (long)(bm + r0);
    long ar1 = arow ? (long)arow[bm + r1] : (long)(bm + r1);
    const float* Ap0 = A + ar0 * K + kq;
    const float* Ap1 = A + ar1 * K + kq;
    const float* Bp0 = Bm + (long)(bn + r0) * K + kq;
    const float* Bp1 = Bm + (long)(bn + r1) * K + kq;

    float acc[4][4][4];
    #pragma unroll
    for (int i = 0; i < 4; i++)
        #pragma unroll
        for (int j = 0; j < 4; j++)
            #pragma unroll
            for (int q = 0; q < 4; q++) acc[i][j][q] = 0.f;

    for (int k0 = 0; k0 < K; k0 += 16) {
        float4 va0 = *(const float4*)(Ap0 + k0);
        float4 va1 = *(const float4*)(Ap1 + k0);
        float4 vb0 = *(const float4*)(Bp0 + k0);
        float4 vb1 = *(const float4*)(Bp1 + k0);

        uint4 pa0 = make_uint4(f2tf(va0.x), f2tf(va0.y), f2tf(va0.z), f2tf(va0.w));
        uint4 pa1 = make_uint4(f2tf(va1.x), f2tf(va1.y), f2tf(va1.z), f2tf(va1.w));
        uint4 pb0 = make_uint4(f2tf(vb0.x), f2tf(vb0.y), f2tf(vb0.z), f2tf(vb0.w));
        uint4 pb1 = make_uint4(f2tf(vb1.x), f2tf(vb1.y), f2tf(vb1.z), f2tf(vb1.w));

        *(uint4*)&As[r0][kq] = pa0;
        *(uint4*)&As[r1][kq] = pa1;
        *(uint4*)&Bs[r0][kq] = pb0;
        *(uint4*)&Bs[r1][kq] = pb1;
        __syncthreads();

        #pragma unroll
        for (int ks = 0; ks < 16; ks += 8) {
            unsigned af[4][4], bf[4][2];
            #pragma unroll
            for (int i = 0; i < 4; i++) {
                int rb = wm + i * 16 + gid;
                af[i][0] = As[rb][ks + tk];
                af[i][1] = As[rb + 8][ks + tk];
                af[i][2] = As[rb][ks + tk + 4];
                af[i][3] = As[rb + 8][ks + tk + 4];
            }
            #pragma unroll
            for (int j = 0; j < 4; j++) {
                int nb = wn + j * 8 + gid;
                bf[j][0] = Bs[nb][ks + tk];
                bf[j][1] = Bs[nb][ks + tk + 4];
            }
            #pragma unroll
            for (int i = 0; i < 4; i++)
                #pragma unroll
                for (int j = 0; j < 4; j++)
                    MMA_TF32(acc[i][j], af[i], bf[j]);
        }
        __syncthreads();
    }

    // Epilogue: c0,c1 -> (row, 2tk/2tk+1); c2,c3 -> (row+8, same cols)
    #pragma unroll
    for (int i = 0; i < 4; i++) {
        int row = bm + wm + i * 16 + gid;
        #pragma unroll
        for (int j = 0; j < 4; j++) {
            int col = bn + wn + j * 8 + tk * 2;
            float b0v = 0.f, b1v = 0.f;
            if (bias1) { b0v += bias1[col]; b1v += bias1[col + 1]; }
            if (bias2) { b0v += bias2[col]; b1v += bias2[col + 1]; }
            float2 v0 = make_float2(acc[i][j][0] + b0v, acc[i][j][1] + b1v);
            float2 v1 = make_float2(acc[i][j][2] + b0v, acc[i][j][3] + b1v);
            *(float2*)&C[(long)row * N + col]       = v0;
            *(float2*)&C[(long)(row + 8) * N + col] = v1;
        }
    }
}

// ---------------------------------------------------------------------------
// LSTM step (fp32 exact): gates(32 x 4096) = xg[s] + h_in @ w_hh^T, pointwise.
// Block owns 8 h-cols; thread = (b, j). Inner loop vectorized: per 4 k it is
// 1 conflict-free LDS.128 (h) + 4 broadcast LDS.128 (w) + 16 FMA.
// ---------------------------------------------------------------------------
#define KT 128

__global__ __launch_bounds__(256, 2)
void lstm_step(const float* __restrict__ xg,    // + s*B*G
               const float* __restrict__ w_hh,  // (4096,1024)
               const float* __restrict__ h_in,
               float* __restrict__ h_out,
               float* __restrict__ c,
               float* __restrict__ hs,
               int store_off,                   // s-ctx, or -1
               int Sact)
{
    __shared__ float sh[32][KT + 4];   // [b][k]
    __shared__ float sw[32][KT + 4];   // [r][k], r = gate*8 + j

    const int t  = threadIdx.x;
    const int b  = t & 31;
    const int j  = t >> 5;           // 0..7
    const int n0 = blockIdx.x * 8;

    float acc0 = 0.f, acc1 = 0.f, acc2 = 0.f, acc3 = 0.f;

    for (int k0 = 0; k0 < H; k0 += KT) {
        #pragma unroll
        for (int i = 0; i < 4; i++) {
            int g  = t + 256 * i;        // 0..1023 float4 groups
            int rr = g >> 5;             // 0..31
            int kq = (g & 31) * 4;       // 0..124
            *(float4*)&sh[rr][kq] = *(const float4*)&h_in[rr * H + k0 + kq];
            int gate = rr >> 3;
            int jj   = rr & 7;
            *(float4*)&sw[rr][kq] =
                *(const float4*)&w_hh[(long)(gate * H + n0 + jj) * H + k0 + kq];
        }
        __syncthreads();

        #pragma unroll
        for (int k = 0; k < KT; k += 4) {
            float4 hv = *(float4*)&sh[b][k];
            float4 w0 = *(float4*)&sw[j][k];
            float4 w1 = *(float4*)&sw[8 + j][k];
            float4 w2 = *(float4*)&sw[16 + j][k];
            float4 w3 = *(float4*)&sw[24 + j][k];
            acc0 += hv.x * w0.x + hv.y * w0.y + hv.z * w0.z + hv.w * w0.w;
            acc1 += hv.x * w1.x + hv.y * w1.y + hv.z * w1.z + hv.w * w1.w;
            acc2 += hv.x * w2.x + hv.y * w2.y + hv.z * w2.z + hv.w * w2.w;
            acc3 += hv.x * w3.x + hv.y * w3.y + hv.z * w3.z + hv.w * w3.w;
        }
        __syncthreads();
    }

    const int n = n0 + j;
    float gi = acc0 + xg[b * G + n];
    float gf = acc1 + xg[b * G + H + n];
    float gg = acc2 + xg[b * G + 2 * H + n];
    float go = acc3 + xg[b * G + 3 * H + n];

    float iv = 1.f / (1.f + expf(-gi));
    float fv = 1.f / (1.f + expf(-gf));
    float gv = tanhf(gg);
    float ov = 1.f / (1.f + expf(-go));

    int cidx = b * H + n;
    float cv = fv * c[cidx] + iv * gv;
    c[cidx] = cv;
    float hv = ov * tanhf(cv);
    h_out[cidx] = hv;

    if (store_off >= 0)
        hs[((long)b * Sact + store_off) * H + n] = hv;
}

// ---------------------------------------------------------------------------
// Launch
// ---------------------------------------------------------------------------
extern "C" void kernel_launch(void* const* d_in, const int* in_sizes, int n_in,
                              void* d_out, int out_size)
{
    const int*   ids   = (const int*)  d_in[0];
    const float* emb   = (const float*)d_in[1];
    const float* w_ih  = (const float*)d_in[2];
    const float* w_hh  = (const float*)d_in[3];
    const float* b_ih  = (const float*)d_in[4];
    const float* b_hh  = (const float*)d_in[5];
    const float* w_out = (const float*)d_in[6];
    const float* b_out = (const float*)d_in[7];

    int ctx  = S - (int)((long)out_size / ((long)B * V));   // = 40
    int Sact = S - ctx;                                     // = 88

    float* xg;     cudaGetSymbolAddress((void**)&xg,     d_xg);
    float* hbuf;   cudaGetSymbolAddress((void**)&hbuf,   d_hbuf);
    float* cbuf;   cudaGetSymbolAddress((void**)&cbuf,   d_cbuf);
    float* hs;     cudaGetSymbolAddress((void**)&hs,     d_hs);
    int*   rowids; cudaGetSymbolAddress((void**)&rowids, d_rowids);

    // 1) init h0/c, gather indices
    init_kernel<<<(B * H + 255) / 256, 256>>>(ids, rowids, hbuf, cbuf);

    // 2) x_gates = gather(emb, ids) @ w_ih^T + b_ih + b_hh   (4096 x 4096 x 1024, tf32)
    gemm_tf32<<<dim3(G / 128, (S * B) / 128), 256>>>(
        emb, w_ih, b_ih, b_hh, xg, S * B, G, I_DIM, rowids);

    // 3) sequential scan (fp32 exact)
    for (int s = 0; s < S; s++) {
        const float* h_in = hbuf + (size_t)(s & 1) * (B * H);
        float* h_out      = hbuf + (size_t)((s + 1) & 1) * (B * H);
        lstm_step<<<H / 8, 256>>>(
            xg + (size_t)s * B * G, w_hh, h_in, h_out, cbuf, hs,
            (s >= ctx) ? (s - ctx) : -1, Sact);
    }

    // 4) logits = hs_flat @ w_out^T + b_out   (2816 x 32000 x 1024, tf32)
    gemm_tf32<<<dim3(V / 128, (B * Sact) / 128), 256>>>(
        hs, w_out, b_out, nullptr, (float*)d_out, B * Sact, V, H, nullptr);
}

// round 5
// speedup vs baseline: 2.8259x; 1.1539x over previous
#include <cuda_runtime.h>
#include <cuda_bf16.h>
#include <math.h>

// Problem constants (fixed by setup_inputs)
#define B   32
#define S   128
#define I_DIM 1024
#define H   1024
#define G   4096      // 4*H
#define V   32000

// ---------------------------------------------------------------------------
// Scratch (static __device__ arrays; no allocation allowed)
// ---------------------------------------------------------------------------
__device__ float d_xg[(size_t)S * B * G];             // precomputed input gates (S,B,4H)
__device__ float d_cbuf[B * H];                       // cell state
__device__ float d_hs[(size_t)B * S * H];             // stored h, layout (b, s', H)
__device__ int   d_rowids[S * B];                     // gather indices for embed GEMM
__device__ __nv_bfloat16 d_whi[(size_t)G * H];        // w_hh hi split (bf16)
__device__ __nv_bfloat16 d_wlo[(size_t)G * H];        // w_hh lo split (bf16)
__device__ __nv_bfloat16 d_hhi[2][B * H];             // h hi split, ping-pong
__device__ __nv_bfloat16 d_hlo[2][B * H];             // h lo split, ping-pong

// ---------------------------------------------------------------------------
// Init: zero h0 splits / c, build gather row ids.  m = s*B + b -> ids[b*S+s]
// ---------------------------------------------------------------------------
__global__ void init_kernel(const int* __restrict__ ids, int* __restrict__ rowids,
                            __nv_bfloat16* __restrict__ hhi,
                            __nv_bfloat16* __restrict__ hlo,
                            float* __restrict__ c)
{
    int t = blockIdx.x * blockDim.x + threadIdx.x;
    if (t < S * B) {
        int s = t >> 5;
        int b = t & 31;
        rowids[t] = ids[b * S + s];
    }
    if (t < B * H) {
        hhi[t] = __float2bfloat16(0.f);
        hlo[t] = __float2bfloat16(0.f);
        c[t]   = 0.f;
    }
}

// ---------------------------------------------------------------------------
// Split w_hh into bf16 hi/lo pair (hi + lo ~ fp32 to ~2^-17)
// ---------------------------------------------------------------------------
__global__ void wsplit_kernel(const float* __restrict__ w,
                              __nv_bfloat16* __restrict__ hi,
                              __nv_bfloat16* __restrict__ lo, int n)
{
    int i = blockIdx.x * blockDim.x + threadIdx.x;
    if (i < n) {
        float v = w[i];
        __nv_bfloat16 h = __float2bfloat16(v);
        hi[i] = h;
        lo[i] = __float2bfloat16(v - __bfloat162float(h));
    }
}

// ---------------------------------------------------------------------------
// tf32 helpers (big GEMMs)
// ---------------------------------------------------------------------------
__device__ __forceinline__ unsigned f2tf(float f) {
    unsigned r;
    asm("cvt.rna.tf32.f32 %0, %1;" : "=r"(r) : "f"(f));
    return r;
}

#define MMA_TF32(d, a, b)                                                     \
    asm volatile(                                                             \
        "mma.sync.aligned.m16n8k8.row.col.f32.tf32.tf32.f32 "                 \
        "{%0,%1,%2,%3}, {%4,%5,%6,%7}, {%8,%9}, {%0,%1,%2,%3};\n"             \
        : "+f"(d[0]), "+f"(d[1]), "+f"(d[2]), "+f"(d[3])                      \
        : "r"(a[0]), "r"(a[1]), "r"(a[2]), "r"(a[3]), "r"(b[0]), "r"(b[1]))

#define MMA_BF16(d, a, b)                                                     \
    asm volatile(                                                             \
        "mma.sync.aligned.m16n8k16.row.col.f32.bf16.bf16.f32 "                \
        "{%0,%1,%2,%3}, {%4,%5,%6,%7}, {%8,%9}, {%0,%1,%2,%3};\n"             \
        : "+f"(d[0]), "+f"(d[1]), "+f"(d[2]), "+f"(d[3])                      \
        : "r"(a[0]), "r"(a[1]), "r"(a[2]), "r"(a[3]), "r"(b[0]), "r"(b[1]))

// ---------------------------------------------------------------------------
// tf32 tensor-core GEMM (unchanged from R3): C = A[row(m)] . Bm^T (+biases)
// ---------------------------------------------------------------------------
__global__ __launch_bounds__(256)
void gemm_tf32(const float* __restrict__ A, const float* __restrict__ Bm,
               const float* __restrict__ bias1, const float* __restrict__ bias2,
               float* __restrict__ C,
               int M, int N, int K,
               const int* __restrict__ arow)
{
    __shared__ unsigned As[128][20];
    __shared__ unsigned Bs[128][20];

    const int bm = blockIdx.y * 128;
    const int bn = blockIdx.x * 128;
    const int t    = threadIdx.x;
    const int lane = t & 31;
    const int w    = t >> 5;
    const int wm   = (w >> 2) * 64;
    const int wn   = (w & 3) * 32;
    const int gid  = lane >> 2;
    const int tk   = lane & 3;

    const int r0 = t >> 2;
    const int r1 = r0 + 64;
    const int kq = (t & 3) * 4;

    long ar0 = arow ? (long)arow[bm + r0] : (long)(bm + r0);
    long ar1 = arow ? (long)arow[bm + r1] : (long)(bm + r1);
    const float* Ap0 = A + ar0 * K + kq;
    const float* Ap1 = A + ar1 * K + kq;
    const float* Bp0 = Bm + (long)(bn + r0) * K + kq;
    const float* Bp1 = Bm + (long)(bn + r1) * K + kq;

    float acc[4][4][4];
    #pragma unroll
    for (int i = 0; i < 4; i++)
        #pragma unroll
        for (int j = 0; j < 4; j++)
            #pragma unroll
            for (int q = 0; q < 4; q++) acc[i][j][q] = 0.f;

    for (int k0 = 0; k0 < K; k0 += 16) {
        float4 va0 = *(const float4*)(Ap0 + k0);
        float4 va1 = *(const float4*)(Ap1 + k0);
        float4 vb0 = *(const float4*)(Bp0 + k0);
        float4 vb1 = *(const float4*)(Bp1 + k0);

        uint4 pa0 = make_uint4(f2tf(va0.x), f2tf(va0.y), f2tf(va0.z), f2tf(va0.w));
        uint4 pa1 = make_uint4(f2tf(va1.x), f2tf(va1.y), f2tf(va1.z), f2tf(va1.w));
        uint4 pb0 = make_uint4(f2tf(vb0.x), f2tf(vb0.y), f2tf(vb0.z), f2tf(vb0.w));
        uint4 pb1 = make_uint4(f2tf(vb1.x), f2tf(vb1.y), f2tf(vb1.z), f2tf(vb1.w));

        *(uint4*)&As[r0][kq] = pa0;
        *(uint4*)&As[r1][kq] = pa1;
        *(uint4*)&Bs[r0][kq] = pb0;
        *(uint4*)&Bs[r1][kq] = pb1;
        __syncthreads();

        #pragma unroll
        for (int ks = 0; ks < 16; ks += 8) {
            unsigned af[4][4], bf[4][2];
            #pragma unroll
            for (int i = 0; i < 4; i++) {
                int rb = wm + i * 16 + gid;
                af[i][0] = As[rb][ks + tk];
                af[i][1] = As[rb + 8][ks + tk];
                af[i][2] = As[rb][ks + tk + 4];
                af[i][3] = As[rb + 8][ks + tk + 4];
            }
            #pragma unroll
            for (int j = 0; j < 4; j++) {
                int nb = wn + j * 8 + gid;
                bf[j][0] = Bs[nb][ks + tk];
                bf[j][1] = Bs[nb][ks + tk + 4];
            }
            #pragma unroll
            for (int i = 0; i < 4; i++)
                #pragma unroll
                for (int j = 0; j < 4; j++)
                    MMA_TF32(acc[i][j], af[i], bf[j]);
        }
        __syncthreads();
    }

    #pragma unroll
    for (int i = 0; i < 4; i++) {
        int row = bm + wm + i * 16 + gid;
        #pragma unroll
        for (int j = 0; j < 4; j++) {
            int col = bn + wn + j * 8 + tk * 2;
            float b0v = 0.f, b1v = 0.f;
            if (bias1) { b0v += bias1[col]; b1v += bias1[col + 1]; }
            if (bias2) { b0v += bias2[col]; b1v += bias2[col + 1]; }
            float2 v0 = make_float2(acc[i][j][0] + b0v, acc[i][j][1] + b1v);
            float2 v1 = make_float2(acc[i][j][2] + b0v, acc[i][j][3] + b1v);
            *(float2*)&C[(long)row * N + col]       = v0;
            *(float2*)&C[(long)(row + 8) * N + col] = v1;
        }
    }
}

// ---------------------------------------------------------------------------
// Tensor-core LSTM step.
// gates(32 x 4096) = (h_hi+h_lo) @ (W_hi+W_lo)^T + xg[s], fused pointwise.
// Block owns 8 h-cols (n0..n0+7) -> 32 gate rows {g*H + n0 + j}.
// 8 warps = 2 m-halves (16 b) x 4 gates. mma m16n8k16 bf16, 3 split terms.
// K chunked by 64, smem rows padded to 36 words (bank = 4*gid+tk, no conflicts).
// ---------------------------------------------------------------------------
#define KC 64
#define NCHUNK (H / KC)   // 16

__global__ __launch_bounds__(256, 1)
void lstm_step_tc(const float* __restrict__ xg,            // + s*B*G
                  const __nv_bfloat16* __restrict__ whi,   // (4096,1024)
                  const __nv_bfloat16* __restrict__ wlo,
                  const __nv_bfloat16* __restrict__ hhi_in,
                  const __nv_bfloat16* __restrict__ hlo_in,
                  __nv_bfloat16* __restrict__ hhi_out,
                  __nv_bfloat16* __restrict__ hlo_out,
                  float* __restrict__ c,
                  float* __restrict__ hs,
                  int store_off, int Sact)
{
    __shared__ __align__(16) unsigned sh_hi[32][36];  // h hi:  [b][k-word], word = 2 bf16
    __shared__ __align__(16) unsigned sh_lo[32][36];
    __shared__ __align__(16) unsigned sw_hi[32][36];  // w:     [gate*8+j][k-word]
    __shared__ __align__(16) unsigned sw_lo[32][36];
    __shared__ float sgate[4][32][8];                 // [gate][b][col]

    const int t    = threadIdx.x;
    const int lane = t & 31;
    const int w    = t >> 5;
    const int wm   = (w >> 2) * 16;   // m-half base (0 or 16)
    const int g    = w & 3;           // gate
    const int gid  = lane >> 2;
    const int tk   = lane & 3;
    const int n0   = blockIdx.x * 8;

    // staging mapping: 256 threads = 32 rows x 8 uint4-chunks (8 bf16 each)
    const int sr = t >> 3;            // smem row 0..31
    const int sq = (t & 7) * 4;       // word offset within row (uint4)
    const int wrow = (sr >> 3) * H + n0 + (sr & 7);   // W row for sw row sr

    const uint4* gWhi = (const uint4*)(whi + (long)wrow * H) + (t & 7);
    const uint4* gWlo = (const uint4*)(wlo + (long)wrow * H) + (t & 7);
    const uint4* gHhi = (const uint4*)(hhi_in + sr * H) + (t & 7);
    const uint4* gHlo = (const uint4*)(hlo_in + sr * H) + (t & 7);
    // per chunk: +8 uint4 (64 bf16)

    float acc[4] = {0.f, 0.f, 0.f, 0.f};

    // prefetch chunk 0
    uint4 rh = gHhi[0], rl = gHlo[0], rwh = gWhi[0], rwl = gWlo[0];

    for (int ch = 0; ch < NCHUNK; ch++) {
        __syncthreads();   // previous chunk's frags consumed
        *(uint4*)&sh_hi[sr][sq] = rh;
        *(uint4*)&sh_lo[sr][sq] = rl;
        *(uint4*)&sw_hi[sr][sq] = rwh;
        *(uint4*)&sw_lo[sr][sq] = rwl;
        __syncthreads();

        if (ch + 1 < NCHUNK) {   // prefetch next chunk (hides L2 latency)
            int off = (ch + 1) * 8;
            rh  = gHhi[off];
            rl  = gHlo[off];
            rwh = gWhi[off];
            rwl = gWlo[off];
        }

        #pragma unroll
        for (int ks = 0; ks < KC / 16; ks++) {
            const int kb = ks * 8;
            const int r0 = wm + gid, r1 = wm + gid + 8;
            const int br = g * 8 + gid;
            unsigned ahi[4], alo[4], bhi[2], blo[2];
            ahi[0] = sh_hi[r0][kb + tk];     ahi[1] = sh_hi[r1][kb + tk];
            ahi[2] = sh_hi[r0][kb + tk + 4]; ahi[3] = sh_hi[r1][kb + tk + 4];
            alo[0] = sh_lo[r0][kb + tk];     alo[1] = sh_lo[r1][kb + tk];
            alo[2] = sh_lo[r0][kb + tk + 4]; alo[3] = sh_lo[r1][kb + tk + 4];
            bhi[0] = sw_hi[br][kb + tk];     bhi[1] = sw_hi[br][kb + tk + 4];
            blo[0] = sw_lo[br][kb + tk];     blo[1] = sw_lo[br][kb + tk + 4];
            MMA_BF16(acc, ahi, bhi);
            MMA_BF16(acc, alo, bhi);
            MMA_BF16(acc, ahi, blo);
        }
    }

    // exchange: acc -> sgate[g][b][col]
    sgate[g][wm + gid][2 * tk]         = acc[0];
    sgate[g][wm + gid][2 * tk + 1]     = acc[1];
    sgate[g][wm + gid + 8][2 * tk]     = acc[2];
    sgate[g][wm + gid + 8][2 * tk + 1] = acc[3];
    __syncthreads();

    // fused pointwise: thread = (b, j)
    const int b = t & 31;
    const int j = t >> 5;
    const int n = n0 + j;

    float gi = sgate[0][b][j] + xg[b * G + n];
    float gf = sgate[1][b][j] + xg[b * G + H + n];
    float gg = sgate[2][b][j] + xg[b * G + 2 * H + n];
    float go = sgate[3][b][j] + xg[b * G + 3 * H + n];

    float iv = 1.f / (1.f + expf(-gi));
    float fv = 1.f / (1.f + expf(-gf));
    float gv = tanhf(gg);
    float ov = 1.f / (1.f + expf(-go));

    int cidx = b * H + n;
    float cv = fv * c[cidx] + iv * gv;
    c[cidx] = cv;
    float hv = ov * tanhf(cv);

    __nv_bfloat16 hb = __float2bfloat16(hv);
    hhi_out[cidx] = hb;
    hlo_out[cidx] = __float2bfloat16(hv - __bfloat162float(hb));

    if (store_off >= 0)
        hs[((long)b * Sact + store_off) * H + n] = hv;
}

// ---------------------------------------------------------------------------
// Launch
// ---------------------------------------------------------------------------
extern "C" void kernel_launch(void* const* d_in, const int* in_sizes, int n_in,
                              void* d_out, int out_size)
{
    const int*   ids   = (const int*)  d_in[0];
    const float* emb   = (const float*)d_in[1];
    const float* w_ih  = (const float*)d_in[2];
    const float* w_hh  = (const float*)d_in[3];
    const float* b_ih  = (const float*)d_in[4];
    const float* b_hh  = (const float*)d_in[5];
    const float* w_out = (const float*)d_in[6];
    const float* b_out = (const float*)d_in[7];

    int ctx  = S - (int)((long)out_size / ((long)B * V));   // = 40
    int Sact = S - ctx;                                     // = 88

    float* xg;   cudaGetSymbolAddress((void**)&xg,   d_xg);
    float* cbuf; cudaGetSymbolAddress((void**)&cbuf, d_cbuf);
    float* hs;   cudaGetSymbolAddress((void**)&hs,   d_hs);
    int* rowids; cudaGetSymbolAddress((void**)&rowids, d_rowids);
    __nv_bfloat16* whi; cudaGetSymbolAddress((void**)&whi, d_whi);
    __nv_bfloat16* wlo; cudaGetSymbolAddress((void**)&wlo, d_wlo);
    __nv_bfloat16* hhi; cudaGetSymbolAddress((void**)&hhi, d_hhi);
    __nv_bfloat16* hlo; cudaGetSymbolAddress((void**)&hlo, d_hlo);

    // 1) init h0 splits / c, gather indices; split w_hh into bf16 hi/lo
    init_kernel<<<(B * H + 255) / 256, 256>>>(ids, rowids, hhi, hlo, cbuf);
    wsplit_kernel<<<(G * H + 255) / 256, 256>>>(w_hh, whi, wlo, G * H);

    // 2) x_gates = gather(emb, ids) @ w_ih^T + b_ih + b_hh   (tf32)
    gemm_tf32<<<dim3(G / 128, (S * B) / 128), 256>>>(
        emb, w_ih, b_ih, b_hh, xg, S * B, G, I_DIM, rowids);

    // 3) sequential scan (bf16-split tensor cores, fp32-accurate)
    for (int s = 0; s < S; s++) {
        int pi = s & 1, po = (s + 1) & 1;
        lstm_step_tc<<<H / 8, 256>>>(
            xg + (size_t)s * B * G, whi, wlo,
            hhi + (size_t)pi * (B * H), hlo + (size_t)pi * (B * H),
            hhi + (size_t)po * (B * H), hlo + (size_t)po * (B * H),
            cbuf, hs, (s >= ctx) ? (s - ctx) : -1, Sact);
    }

    // 4) logits = hs_flat @ w_out^T + b_out   (tf32)
    gemm_tf32<<<dim3(V / 128, (B * Sact) / 128), 256>>>(
        hs, w_out, b_out, nullptr, (float*)d_out, B * Sact, V, H, nullptr);
}

// round 7
// speedup vs baseline: 3.3891x; 1.1993x over previous
#include <cuda_runtime.h>
#include <cuda_bf16.h>
#include <math.h>

// Problem constants (fixed by setup_inputs)
#define B   32
#define S   128
#define I_DIM 1024
#define H   1024
#define G   4096      // 4*H
#define V   32000
#define NB  128       // scan grid (H/8), all co-resident (< 148 SMs, 1 blk/SM)

// ---------------------------------------------------------------------------
// Scratch (static __device__ arrays; no allocation allowed)
// ---------------------------------------------------------------------------
__device__ float d_xg[(size_t)S * B * G];             // precomputed input gates (S,B,4H)
__device__ float d_hs[(size_t)B * S * H];             // stored h, layout (b, s', H)
__device__ int   d_rowids[S * B];                     // gather indices for embed GEMM
__device__ __nv_bfloat16 d_whi[(size_t)G * H];        // w_hh hi split (bf16)
__device__ __nv_bfloat16 d_wlo[(size_t)G * H];        // w_hh lo split (bf16)
__device__ __nv_bfloat16 d_hhi[2][B * H];             // h hi split, ping-pong
__device__ __nv_bfloat16 d_hlo[2][B * H];             // h lo split, ping-pong
__device__ unsigned g_arrive;                         // grid-barrier arrival counter

// ---------------------------------------------------------------------------
// Init: zero h0 splits, reset barrier, build gather row ids.
// ---------------------------------------------------------------------------
__global__ void init_kernel(const int* __restrict__ ids, int* __restrict__ rowids,
                            __nv_bfloat16* __restrict__ hhi,
                            __nv_bfloat16* __restrict__ hlo)
{
    int t = blockIdx.x * blockDim.x + threadIdx.x;
    if (t == 0) g_arrive = 0u;
    if (t < S * B) {
        int s = t >> 5;
        int b = t & 31;
        rowids[t] = ids[b * S + s];
    }
    if (t < B * H) {
        hhi[t] = __float2bfloat16(0.f);
        hlo[t] = __float2bfloat16(0.f);
    }
}

// ---------------------------------------------------------------------------
// Split w_hh into bf16 hi/lo pair (hi + lo ~ fp32 to ~2^-17)
// ---------------------------------------------------------------------------
__global__ void wsplit_kernel(const float* __restrict__ w,
                              __nv_bfloat16* __restrict__ hi,
                              __nv_bfloat16* __restrict__ lo, int n)
{
    int i = blockIdx.x * blockDim.x + threadIdx.x;
    if (i < n) {
        float v = w[i];
        __nv_bfloat16 h = __float2bfloat16(v);
        hi[i] = h;
        lo[i] = __float2bfloat16(v - __bfloat162float(h));
    }
}

// ---------------------------------------------------------------------------
// mma helpers
// ---------------------------------------------------------------------------
__device__ __forceinline__ unsigned f2tf(float f) {
    unsigned r;
    asm("cvt.rna.tf32.f32 %0, %1;" : "=r"(r) : "f"(f));
    return r;
}

#define MMA_TF32(d, a, b)                                                     \
    asm volatile(                                                             \
        "mma.sync.aligned.m16n8k8.row.col.f32.tf32.tf32.f32 "                 \
        "{%0,%1,%2,%3}, {%4,%5,%6,%7}, {%8,%9}, {%0,%1,%2,%3};\n"             \
        : "+f"(d[0]), "+f"(d[1]), "+f"(d[2]), "+f"(d[3])                      \
        : "r"(a[0]), "r"(a[1]), "r"(a[2]), "r"(a[3]), "r"(b[0]), "r"(b[1]))

#define MMA_BF16(d, a, b)                                                     \
    asm volatile(                                                             \
        "mma.sync.aligned.m16n8k16.row.col.f32.bf16.bf16.f32 "                \
        "{%0,%1,%2,%3}, {%4,%5,%6,%7}, {%8,%9}, {%0,%1,%2,%3};\n"             \
        : "+f"(d[0]), "+f"(d[1]), "+f"(d[2]), "+f"(d[3])                      \
        : "r"(a[0]), "r"(a[1]), "r"(a[2]), "r"(a[3]), "r"(b[0]), "r"(b[1]))

// ---------------------------------------------------------------------------
// tf32 tensor-core GEMM (unchanged, known-good): C = A[row(m)] . Bm^T (+biases)
// ---------------------------------------------------------------------------
__global__ __launch_bounds__(256)
void gemm_tf32(const float* __restrict__ A, const float* __restrict__ Bm,
               const float* __restrict__ bias1, const float* __restrict__ bias2,
               float* __restrict__ C,
               int M, int N, int K,
               const int* __restrict__ arow)
{
    __shared__ unsigned As[128][20];
    __shared__ unsigned Bs[128][20];

    const int bm = blockIdx.y * 128;
    const int bn = blockIdx.x * 128;
    const int t    = threadIdx.x;
    const int lane = t & 31;
    const int w    = t >> 5;
    const int wm   = (w >> 2) * 64;
    const int wn   = (w & 3) * 32;
    const int gid  = lane >> 2;
    const int tk   = lane & 3;

    const int r0 = t >> 2;
    const int r1 = r0 + 64;
    const int kq = (t & 3) * 4;

    long ar0 = arow ? (long)arow[bm + r0] : (long)(bm + r0);
    long ar1 = arow ? (long)arow[bm + r1] : (long)(bm + r1);
    const float* Ap0 = A + ar0 * K + kq;
    const float* Ap1 = A + ar1 * K + kq;
    const float* Bp0 = Bm + (long)(bn + r0) * K + kq;
    const float* Bp1 = Bm + (long)(bn + r1) * K + kq;

    float acc[4][4][4];
    #pragma unroll
    for (int i = 0; i < 4; i++)
        #pragma unroll
        for (int j = 0; j < 4; j++)
            #pragma unroll
            for (int q = 0; q < 4; q++) acc[i][j][q] = 0.f;

    for (int k0 = 0; k0 < K; k0 += 16) {
        float4 va0 = *(const float4*)(Ap0 + k0);
        float4 va1 = *(const float4*)(Ap1 + k0);
        float4 vb0 = *(const float4*)(Bp0 + k0);
        float4 vb1 = *(const float4*)(Bp1 + k0);

        uint4 pa0 = make_uint4(f2tf(va0.x), f2tf(va0.y), f2tf(va0.z), f2tf(va0.w));
        uint4 pa1 = make_uint4(f2tf(va1.x), f2tf(va1.y), f2tf(va1.z), f2tf(va1.w));
        uint4 pb0 = make_uint4(f2tf(vb0.x), f2tf(vb0.y), f2tf(vb0.z), f2tf(vb0.w));
        uint4 pb1 = make_uint4(f2tf(vb1.x), f2tf(vb1.y), f2tf(vb1.z), f2tf(vb1.w));

        *(uint4*)&As[r0][kq] = pa0;
        *(uint4*)&As[r1][kq] = pa1;
        *(uint4*)&Bs[r0][kq] = pb0;
        *(uint4*)&Bs[r1][kq] = pb1;
        __syncthreads();

        #pragma unroll
        for (int ks = 0; ks < 16; ks += 8) {
            unsigned af[4][4], bf[4][2];
            #pragma unroll
            for (int i = 0; i < 4; i++) {
                int rb = wm + i * 16 + gid;
                af[i][0] = As[rb][ks + tk];
                af[i][1] = As[rb + 8][ks + tk];
                af[i][2] = As[rb][ks + tk + 4];
                af[i][3] = As[rb + 8][ks + tk + 4];
            }
            #pragma unroll
            for (int j = 0; j < 4; j++) {
                int nb = wn + j * 8 + gid;
                bf[j][0] = Bs[nb][ks + tk];
                bf[j][1] = Bs[nb][ks + tk + 4];
            }
            #pragma unroll
            for (int i = 0; i < 4; i++)
                #pragma unroll
                for (int j = 0; j < 4; j++)
                    MMA_TF32(acc[i][j], af[i], bf[j]);
        }
        __syncthreads();
    }

    #pragma unroll
    for (int i = 0; i < 4; i++) {
        int row = bm + wm + i * 16 + gid;
        #pragma unroll
        for (int j = 0; j < 4; j++) {
            int col = bn + wn + j * 8 + tk * 2;
            float b0v = 0.f, b1v = 0.f;
            if (bias1) { b0v += bias1[col]; b1v += bias1[col + 1]; }
            if (bias2) { b0v += bias2[col]; b1v += bias2[col + 1]; }
            float2 v0 = make_float2(acc[i][j][0] + b0v, acc[i][j][1] + b1v);
            float2 v1 = make_float2(acc[i][j][2] + b0v, acc[i][j][3] + b1v);
            *(float2*)&C[(long)row * N + col]       = v0;
            *(float2*)&C[(long)(row + 8) * N + col] = v1;
        }
    }
}

// ---------------------------------------------------------------------------
// Persistent tensor-core LSTM scan: ALL 128 steps in one kernel.
// Block bx owns h-cols n0..n0+7 (32 gate rows). Its W slice (bf16 hi/lo,
// 128 KB) lives in SMEM for the whole kernel. Per step: stream h (L2, __ldcg
// to bypass incoherent L1), 3-term split MMA, fused pointwise with c in a
// register, software grid barrier (all 128 blocks co-resident).
// ---------------------------------------------------------------------------
#define KC 64
#define NCHUNK (H / KC)   // 16
#define WPITCH 36         // padded row pitch in 32-bit words (conflict-free)

// dynamic smem words: W hi/lo [NCHUNK][32][WPITCH] x2, h staging x2 bufs x2
// splits, gate exchange 4*32*8 floats
#define SCAN_SMEM_BYTES ((2 * NCHUNK * 32 * WPITCH + 4 * 32 * WPITCH) * 4 + 4 * 32 * 8 * 4)

__global__ __launch_bounds__(256, 1)
void lstm_scan(const float* __restrict__ xg_base,
               const __nv_bfloat16* __restrict__ whi,
               const __nv_bfloat16* __restrict__ wlo,
               __nv_bfloat16* __restrict__ hhi,   // [2][B*H] ping-pong
               __nv_bfloat16* __restrict__ hlo,
               float* __restrict__ hs,
               int ctx, int Sact)
{
    extern __shared__ unsigned sm[];
    unsigned* wh  = sm;                            // [NCHUNK][32][WPITCH]
    unsigned* wl  = wh + NCHUNK * 32 * WPITCH;
    unsigned* shb = wl + NCHUNK * 32 * WPITCH;     // [2][32][WPITCH]
    unsigned* slb = shb + 2 * 32 * WPITCH;
    float* sgate  = (float*)(slb + 2 * 32 * WPITCH); // [4][32][8]

    const int t    = threadIdx.x;
    const int lane = t & 31;
    const int w    = t >> 5;
    const int wm   = (w >> 2) * 16;   // m-half base (0 or 16)
    const int g    = w & 3;           // gate
    const int gid  = lane >> 2;
    const int tk   = lane & 3;
    const int n0   = blockIdx.x * 8;

    // staging mapping: 256 threads = 32 rows x 8 uint4 (8 bf16) chunks
    const int sr   = t >> 3;
    const int sq   = (t & 7) * 4;
    const int wrow = (sr >> 3) * H + n0 + (sr & 7);

    // --- load this block's W slice into persistent smem (once) ---
    const uint4* gWhi = (const uint4*)(whi + (long)wrow * H) + (t & 7);
    const uint4* gWlo = (const uint4*)(wlo + (long)wrow * H) + (t & 7);
    #pragma unroll 4
    for (int ch = 0; ch < NCHUNK; ch++) {
        *(uint4*)&wh[(ch * 32 + sr) * WPITCH + sq] = gWhi[ch * 8];
        *(uint4*)&wl[(ch * 32 + sr) * WPITCH + sq] = gWlo[ch * 8];
    }

    const int b = t & 31;
    const int j = t >> 5;
    const int n = n0 + j;
    float cval  = 0.f;
    const float* xgp = xg_base + b * G + n;

    __syncthreads();

    for (int s = 0; s < S; s++) {
        const int pi = s & 1;
        const uint4* gHhi = (const uint4*)(hhi + (size_t)pi * (B * H) + sr * H) + (t & 7);
        const uint4* gHlo = (const uint4*)(hlo + (size_t)pi * (B * H) + sr * H) + (t & 7);

        uint4 rh = __ldcg(gHhi);
        uint4 rl = __ldcg(gHlo);

        float acc[4] = {0.f, 0.f, 0.f, 0.f};

        for (int ch = 0; ch < NCHUNK; ch++) {
            const int buf = ch & 1;
            unsigned* sh = shb + buf * 32 * WPITCH;
            unsigned* sl = slb + buf * 32 * WPITCH;
            *(uint4*)&sh[sr * WPITCH + sq] = rh;
            *(uint4*)&sl[sr * WPITCH + sq] = rl;
            __syncthreads();

            if (ch + 1 < NCHUNK) {            // prefetch next h chunk
                rh = __ldcg(gHhi + (ch + 1) * 8);
                rl = __ldcg(gHlo + (ch + 1) * 8);
            }

            const unsigned* whc = wh + ch * 32 * WPITCH;
            const unsigned* wlc = wl + ch * 32 * WPITCH;
            #pragma unroll
            for (int ks = 0; ks < KC / 16; ks++) {
                const int kb = ks * 8;
                const int r0 = wm + gid, r1 = r0 + 8;
                const int br = g * 8 + gid;
                unsigned ahi[4], alo[4], bhi[2], blo[2];
                ahi[0] = sh[r0 * WPITCH + kb + tk];
                ahi[1] = sh[r1 * WPITCH + kb + tk];
                ahi[2] = sh[r0 * WPITCH + kb + tk + 4];
                ahi[3] = sh[r1 * WPITCH + kb + tk + 4];
                alo[0] = sl[r0 * WPITCH + kb + tk];
                alo[1] = sl[r1 * WPITCH + kb + tk];
                alo[2] = sl[r0 * WPITCH + kb + tk + 4];
                alo[3] = sl[r1 * WPITCH + kb + tk + 4];
                bhi[0] = whc[br * WPITCH + kb + tk];
                bhi[1] = whc[br * WPITCH + kb + tk + 4];
                blo[0] = wlc[br * WPITCH + kb + tk];
                blo[1] = wlc[br * WPITCH + kb + tk + 4];
                MMA_BF16(acc, ahi, bhi);
                MMA_BF16(acc, alo, bhi);
                MMA_BF16(acc, ahi, blo);
            }
        }

        // gate exchange
        __syncthreads();
        sgate[(g * 32 + wm + gid) * 8 + 2 * tk]         = acc[0];
        sgate[(g * 32 + wm + gid) * 8 + 2 * tk + 1]     = acc[1];
        sgate[(g * 32 + wm + gid + 8) * 8 + 2 * tk]     = acc[2];
        sgate[(g * 32 + wm + gid + 8) * 8 + 2 * tk + 1] = acc[3];
        __syncthreads();

        // fused pointwise: thread = (b, j)
        const float* xgs = xgp + (size_t)s * (B * G);
        float gi = sgate[(0 * 32 + b) * 8 + j] + xgs[0];
        float gf = sgate[(1 * 32 + b) * 8 + j] + xgs[H];
        float gg = sgate[(2 * 32 + b) * 8 + j] + xgs[2 * H];
        float go = sgate[(3 * 32 + b) * 8 + j] + xgs[3 * H];

        float iv = 1.f / (1.f + expf(-gi));
        float fv = 1.f / (1.f + expf(-gf));
        float gv = tanhf(gg);
        float ov = 1.f / (1.f + expf(-go));

        cval = fv * cval + iv * gv;
        float hv = ov * tanhf(cval);

        const int po = (s + 1) & 1;
        const int cidx = b * H + n;
        __nv_bfloat16 hb = __float2bfloat16(hv);
        hhi[(size_t)po * (B * H) + cidx] = hb;
        hlo[(size_t)po * (B * H) + cidx] = __float2bfloat16(hv - __bfloat162float(hb));
        if (s >= ctx)
            hs[((long)b * Sact + (s - ctx)) * H + n] = hv;

        // grid barrier: h_out visible to all blocks before next step
        __threadfence();
        __syncthreads();
        if (t == 0) {
            atomicAdd(&g_arrive, 1u);
            const unsigned bound = (unsigned)NB * (unsigned)(s + 1);
            while (atomicAdd(&g_arrive, 0u) < bound) { __nanosleep(64); }
        }
        __syncthreads();
        __threadfence();
    }
}

// ---------------------------------------------------------------------------
// Launch
// ---------------------------------------------------------------------------
extern "C" void kernel_launch(void* const* d_in, const int* in_sizes, int n_in,
                              void* d_out, int out_size)
{
    const int*   ids   = (const int*)  d_in[0];
    const float* emb   = (const float*)d_in[1];
    const float* w_ih  = (const float*)d_in[2];
    const float* w_hh  = (const float*)d_in[3];
    const float* b_ih  = (const float*)d_in[4];
    const float* b_hh  = (const float*)d_in[5];
    const float* w_out = (const float*)d_in[6];
    const float* b_out = (const float*)d_in[7];

    int ctx  = S - (int)((long)out_size / ((long)B * V));   // = 40
    int Sact = S - ctx;                                     // = 88

    float* xg;   cudaGetSymbolAddress((void**)&xg,   d_xg);
    float* hs;   cudaGetSymbolAddress((void**)&hs,   d_hs);
    int* rowids; cudaGetSymbolAddress((void**)&rowids, d_rowids);
    __nv_bfloat16* whi; cudaGetSymbolAddress((void**)&whi, d_whi);
    __nv_bfloat16* wlo; cudaGetSymbolAddress((void**)&wlo, d_wlo);
    __nv_bfloat16* hhi; cudaGetSymbolAddress((void**)&hhi, d_hhi);
    __nv_bfloat16* hlo; cudaGetSymbolAddress((void**)&hlo, d_hlo);

    static bool attr_set = false;
    if (!attr_set) {
        cudaFuncSetAttribute(lstm_scan, cudaFuncAttributeMaxDynamicSharedMemorySize,
                             SCAN_SMEM_BYTES);
        attr_set = true;
    }

    // 1) init h0 splits / barrier / gather ids; split w_hh into bf16 hi/lo
    init_kernel<<<(B * H + 255) / 256, 256>>>(ids, rowids, hhi, hlo);
    wsplit_kernel<<<(G * H + 255) / 256, 256>>>(w_hh, whi, wlo, G * H);

    // 2) x_gates = gather(emb, ids) @ w_ih^T + b_ih + b_hh   (tf32)
    gemm_tf32<<<dim3(G / 128, (S * B) / 128), 256>>>(
        emb, w_ih, b_ih, b_hh, xg, S * B, G, I_DIM, rowids);

    // 3) persistent scan: all 128 steps, W resident in SMEM
    lstm_scan<<<NB, 256, SCAN_SMEM_BYTES>>>(xg, whi, wlo, hhi, hlo, hs, ctx, Sact);

    // 4) logits = hs_flat @ w_out^T + b_out   (tf32)
    gemm_tf32<<<dim3(V / 128, (B * Sact) / 128), 256>>>(
        hs, w_out, b_out, nullptr, (float*)d_out, B * Sact, V, H, nullptr);
}

// round 8
// speedup vs baseline: 3.7006x; 1.0919x over previous
#include <cuda_runtime.h>
#include <cuda_bf16.h>
#include <math.h>

// Problem constants (fixed by setup_inputs)
#define B   32
#define S   128
#define I_DIM 1024
#define H   1024
#define G   4096      // 4*H
#define V   32000
#define NB  128       // scan grid (H/8), all co-resident (< 148 SMs, 1 blk/SM)

// ---------------------------------------------------------------------------
// Scratch (static __device__ arrays; no allocation allowed)
// ---------------------------------------------------------------------------
__device__ float d_xg[(size_t)S * B * G];             // precomputed input gates (S,B,4H)
__device__ float d_hs[(size_t)B * S * H];             // stored h, layout (b, s', H)
__device__ int   d_rowids[S * B];                     // gather indices for embed GEMM
__device__ __nv_bfloat16 d_whi[(size_t)G * H];        // w_hh hi split (bf16)
__device__ __nv_bfloat16 d_wlo[(size_t)G * H];        // w_hh lo split (bf16)
__device__ __nv_bfloat16 d_hhi[2][B * H];             // h hi split, ping-pong
__device__ __nv_bfloat16 d_hlo[2][B * H];             // h lo split, ping-pong
__device__ unsigned g_arrive;                         // grid-barrier arrival counter

// ---------------------------------------------------------------------------
// Init: zero h0 splits, reset barrier, build gather row ids.
// ---------------------------------------------------------------------------
__global__ void init_kernel(const int* __restrict__ ids, int* __restrict__ rowids,
                            __nv_bfloat16* __restrict__ hhi,
                            __nv_bfloat16* __restrict__ hlo)
{
    int t = blockIdx.x * blockDim.x + threadIdx.x;
    if (t == 0) g_arrive = 0u;
    if (t < S * B) {
        int s = t >> 5;
        int b = t & 31;
        rowids[t] = ids[b * S + s];
    }
    if (t < B * H) {
        hhi[t] = __float2bfloat16(0.f);
        hlo[t] = __float2bfloat16(0.f);
    }
}

// ---------------------------------------------------------------------------
// Split w_hh into bf16 hi/lo pair (hi + lo ~ fp32 to ~2^-17)
// ---------------------------------------------------------------------------
__global__ void wsplit_kernel(const float* __restrict__ w,
                              __nv_bfloat16* __restrict__ hi,
                              __nv_bfloat16* __restrict__ lo, int n)
{
    int i = blockIdx.x * blockDim.x + threadIdx.x;
    if (i < n) {
        float v = w[i];
        __nv_bfloat16 h = __float2bfloat16(v);
        hi[i] = h;
        lo[i] = __float2bfloat16(v - __bfloat162float(h));
    }
}

// ---------------------------------------------------------------------------
// mma helpers
// ---------------------------------------------------------------------------
__device__ __forceinline__ unsigned f2tf(float f) {
    unsigned r;
    asm("cvt.rna.tf32.f32 %0, %1;" : "=r"(r) : "f"(f));
    return r;
}

#define MMA_TF32(d, a, b)                                                     \
    asm volatile(                                                             \
        "mma.sync.aligned.m16n8k8.row.col.f32.tf32.tf32.f32 "                 \
        "{%0,%1,%2,%3}, {%4,%5,%6,%7}, {%8,%9}, {%0,%1,%2,%3};\n"             \
        : "+f"(d[0]), "+f"(d[1]), "+f"(d[2]), "+f"(d[3])                      \
        : "r"(a[0]), "r"(a[1]), "r"(a[2]), "r"(a[3]), "r"(b[0]), "r"(b[1]))

#define MMA_BF16(d, a, b)                                                     \
    asm volatile(                                                             \
        "mma.sync.aligned.m16n8k16.row.col.f32.bf16.bf16.f32 "                \
        "{%0,%1,%2,%3}, {%4,%5,%6,%7}, {%8,%9}, {%0,%1,%2,%3};\n"             \
        : "+f"(d[0]), "+f"(d[1]), "+f"(d[2]), "+f"(d[3])                      \
        : "r"(a[0]), "r"(a[1]), "r"(a[2]), "r"(a[3]), "r"(b[0]), "r"(b[1]))

// ---------------------------------------------------------------------------
// tf32 tensor-core GEMM (unchanged, known-good): C = A[row(m)] . Bm^T (+biases)
// ---------------------------------------------------------------------------
__global__ __launch_bounds__(256)
void gemm_tf32(const float* __restrict__ A, const float* __restrict__ Bm,
               const float* __restrict__ bias1, const float* __restrict__ bias2,
               float* __restrict__ C,
               int M, int N, int K,
               const int* __restrict__ arow)
{
    __shared__ unsigned As[128][20];
    __shared__ unsigned Bs[128][20];

    const int bm = blockIdx.y * 128;
    const int bn = blockIdx.x * 128;
    const int t    = threadIdx.x;
    const int lane = t & 31;
    const int w    = t >> 5;
    const int wm   = (w >> 2) * 64;
    const int wn   = (w & 3) * 32;
    const int gid  = lane >> 2;
    const int tk   = lane & 3;

    const int r0 = t >> 2;
    const int r1 = r0 + 64;
    const int kq = (t & 3) * 4;

    long ar0 = arow ? (long)arow[bm + r0] : (long)(bm + r0);
    long ar1 = arow ? (long)arow[bm + r1] : (long)(bm + r1);
    const float* Ap0 = A + ar0 * K + kq;
    const float* Ap1 = A + ar1 * K + kq;
    const float* Bp0 = Bm + (long)(bn + r0) * K + kq;
    const float* Bp1 = Bm + (long)(bn + r1) * K + kq;

    float acc[4][4][4];
    #pragma unroll
    for (int i = 0; i < 4; i++)
        #pragma unroll
        for (int j = 0; j < 4; j++)
            #pragma unroll
            for (int q = 0; q < 4; q++) acc[i][j][q] = 0.f;

    for (int k0 = 0; k0 < K; k0 += 16) {
        float4 va0 = *(const float4*)(Ap0 + k0);
        float4 va1 = *(const float4*)(Ap1 + k0);
        float4 vb0 = *(const float4*)(Bp0 + k0);
        float4 vb1 = *(const float4*)(Bp1 + k0);

        uint4 pa0 = make_uint4(f2tf(va0.x), f2tf(va0.y), f2tf(va0.z), f2tf(va0.w));
        uint4 pa1 = make_uint4(f2tf(va1.x), f2tf(va1.y), f2tf(va1.z), f2tf(va1.w));
        uint4 pb0 = make_uint4(f2tf(vb0.x), f2tf(vb0.y), f2tf(vb0.z), f2tf(vb0.w));
        uint4 pb1 = make_uint4(f2tf(vb1.x), f2tf(vb1.y), f2tf(vb1.z), f2tf(vb1.w));

        *(uint4*)&As[r0][kq] = pa0;
        *(uint4*)&As[r1][kq] = pa1;
        *(uint4*)&Bs[r0][kq] = pb0;
        *(uint4*)&Bs[r1][kq] = pb1;
        __syncthreads();

        #pragma unroll
        for (int ks = 0; ks < 16; ks += 8) {
            unsigned af[4][4], bf[4][2];
            #pragma unroll
            for (int i = 0; i < 4; i++) {
                int rb = wm + i * 16 + gid;
                af[i][0] = As[rb][ks + tk];
                af[i][1] = As[rb + 8][ks + tk];
                af[i][2] = As[rb][ks + tk + 4];
                af[i][3] = As[rb + 8][ks + tk + 4];
            }
            #pragma unroll
            for (int j = 0; j < 4; j++) {
                int nb = wn + j * 8 + gid;
                bf[j][0] = Bs[nb][ks + tk];
                bf[j][1] = Bs[nb][ks + tk + 4];
            }
            #pragma unroll
            for (int i = 0; i < 4; i++)
                #pragma unroll
                for (int j = 0; j < 4; j++)
                    MMA_TF32(acc[i][j], af[i], bf[j]);
        }
        __syncthreads();
    }

    #pragma unroll
    for (int i = 0; i < 4; i++) {
        int row = bm + wm + i * 16 + gid;
        #pragma unroll
        for (int j = 0; j < 4; j++) {
            int col = bn + wn + j * 8 + tk * 2;
            float b0v = 0.f, b1v = 0.f;
            if (bias1) { b0v += bias1[col]; b1v += bias1[col + 1]; }
            if (bias2) { b0v += bias2[col]; b1v += bias2[col + 1]; }
            float2 v0 = make_float2(acc[i][j][0] + b0v, acc[i][j][1] + b1v);
            float2 v1 = make_float2(acc[i][j][2] + b0v, acc[i][j][3] + b1v);
            *(float2*)&C[(long)row * N + col]       = v0;
            *(float2*)&C[(long)(row + 8) * N + col] = v1;
        }
    }
}

// ---------------------------------------------------------------------------
// Persistent tensor-core LSTM scan (all 128 steps, W resident in SMEM).
// R7 fixes: acquire-load spin barrier (no RMW polling), xg loads hoisted to
// step start, h prefetch distance 2, no trailing fence, __expf sigmoids.
// ---------------------------------------------------------------------------
#define KC 64
#define NCHUNK (H / KC)   // 16
#define WPITCH 36         // padded row pitch in 32-bit words (conflict-free)

#define SCAN_SMEM_BYTES ((2 * NCHUNK * 32 * WPITCH + 4 * 32 * WPITCH) * 4 + 4 * 32 * 8 * 4)

__global__ __launch_bounds__(256, 1)
void lstm_scan(const float* __restrict__ xg_base,
               const __nv_bfloat16* __restrict__ whi,
               const __nv_bfloat16* __restrict__ wlo,
               __nv_bfloat16* __restrict__ hhi,   // [2][B*H] ping-pong
               __nv_bfloat16* __restrict__ hlo,
               float* __restrict__ hs,
               int ctx, int Sact)
{
    extern __shared__ unsigned sm[];
    unsigned* wh  = sm;                            // [NCHUNK][32][WPITCH]
    unsigned* wl  = wh + NCHUNK * 32 * WPITCH;
    unsigned* shb = wl + NCHUNK * 32 * WPITCH;     // [2][32][WPITCH]
    unsigned* slb = shb + 2 * 32 * WPITCH;
    float* sgate  = (float*)(slb + 2 * 32 * WPITCH); // [4][32][8]

    const int t    = threadIdx.x;
    const int lane = t & 31;
    const int w    = t >> 5;
    const int wm   = (w >> 2) * 16;   // m-half base (0 or 16)
    const int g    = w & 3;           // gate
    const int gid  = lane >> 2;
    const int tk   = lane & 3;
    const int n0   = blockIdx.x * 8;

    // staging mapping: 256 threads = 32 rows x 8 uint4 (8 bf16) chunks
    const int sr   = t >> 3;
    const int sq   = (t & 7) * 4;
    const int wrow = (sr >> 3) * H + n0 + (sr & 7);

    // --- load this block's W slice into persistent smem (once) ---
    const uint4* gWhi = (const uint4*)(whi + (long)wrow * H) + (t & 7);
    const uint4* gWlo = (const uint4*)(wlo + (long)wrow * H) + (t & 7);
    #pragma unroll 4
    for (int ch = 0; ch < NCHUNK; ch++) {
        *(uint4*)&wh[(ch * 32 + sr) * WPITCH + sq] = gWhi[ch * 8];
        *(uint4*)&wl[(ch * 32 + sr) * WPITCH + sq] = gWlo[ch * 8];
    }

    const int b = t & 31;
    const int j = t >> 5;
    const int n = n0 + j;
    float cval  = 0.f;
    const float* xgp = xg_base + b * G + n;

    __syncthreads();

    for (int s = 0; s < S; s++) {
        const int pi = s & 1;
        const uint4* gHhi = (const uint4*)(hhi + (size_t)pi * (B * H) + sr * H) + (t & 7);
        const uint4* gHlo = (const uint4*)(hlo + (size_t)pi * (B * H) + sr * H) + (t & 7);

        // hoisted xg loads — independent of h, fully hidden behind chunk loop
        const float* xgs = xgp + (size_t)s * (B * G);
        float xgi = __ldg(xgs);
        float xgf = __ldg(xgs + H);
        float xgg = __ldg(xgs + 2 * H);
        float xgo = __ldg(xgs + 3 * H);

        // prefetch chunks 0 and 1 (distance 2)
        uint4 rh[2], rl[2];
        rh[0] = __ldcg(gHhi);     rl[0] = __ldcg(gHlo);
        rh[1] = __ldcg(gHhi + 8); rl[1] = __ldcg(gHlo + 8);

        float acc[4] = {0.f, 0.f, 0.f, 0.f};

        #pragma unroll
        for (int ch = 0; ch < NCHUNK; ch++) {
            const int buf = ch & 1;
            unsigned* sh = shb + buf * 32 * WPITCH;
            unsigned* sl = slb + buf * 32 * WPITCH;
            *(uint4*)&sh[sr * WPITCH + sq] = rh[buf];
            *(uint4*)&sl[sr * WPITCH + sq] = rl[buf];
            __syncthreads();

            if (ch + 2 < NCHUNK) {            // prefetch 2 chunks ahead
                rh[buf] = __ldcg(gHhi + (ch + 2) * 8);
                rl[buf] = __ldcg(gHlo + (ch + 2) * 8);
            }

            const unsigned* whc = wh + ch * 32 * WPITCH;
            const unsigned* wlc = wl + ch * 32 * WPITCH;
            #pragma unroll
            for (int ks = 0; ks < KC / 16; ks++) {
                const int kb = ks * 8;
                const int r0 = wm + gid, r1 = r0 + 8;
                const int br = g * 8 + gid;
                unsigned ahi[4], alo[4], bhi[2], blo[2];
                ahi[0] = sh[r0 * WPITCH + kb + tk];
                ahi[1] = sh[r1 * WPITCH + kb + tk];
                ahi[2] = sh[r0 * WPITCH + kb + tk + 4];
                ahi[3] = sh[r1 * WPITCH + kb + tk + 4];
                alo[0] = sl[r0 * WPITCH + kb + tk];
                alo[1] = sl[r1 * WPITCH + kb + tk];
                alo[2] = sl[r0 * WPITCH + kb + tk + 4];
                alo[3] = sl[r1 * WPITCH + kb + tk + 4];
                bhi[0] = whc[br * WPITCH + kb + tk];
                bhi[1] = whc[br * WPITCH + kb + tk + 4];
                blo[0] = wlc[br * WPITCH + kb + tk];
                blo[1] = wlc[br * WPITCH + kb + tk + 4];
                MMA_BF16(acc, ahi, bhi);
                MMA_BF16(acc, alo, bhi);
                MMA_BF16(acc, ahi, blo);
            }
        }

        // gate exchange
        __syncthreads();
        sgate[(g * 32 + wm + gid) * 8 + 2 * tk]         = acc[0];
        sgate[(g * 32 + wm + gid) * 8 + 2 * tk + 1]     = acc[1];
        sgate[(g * 32 + wm + gid + 8) * 8 + 2 * tk]     = acc[2];
        sgate[(g * 32 + wm + gid + 8) * 8 + 2 * tk + 1] = acc[3];
        __syncthreads();

        // fused pointwise: thread = (b, j)
        float gi = sgate[(0 * 32 + b) * 8 + j] + xgi;
        float gf = sgate[(1 * 32 + b) * 8 + j] + xgf;
        float gg = sgate[(2 * 32 + b) * 8 + j] + xgg;
        float go = sgate[(3 * 32 + b) * 8 + j] + xgo;

        float iv = 1.f / (1.f + __expf(-gi));
        float fv = 1.f / (1.f + __expf(-gf));
        float gv = tanhf(gg);
        float ov = 1.f / (1.f + __expf(-go));

        cval = fv * cval + iv * gv;
        float hv = ov * tanhf(cval);

        const int po = (s + 1) & 1;
        const int cidx = b * H + n;
        __nv_bfloat16 hb = __float2bfloat16(hv);
        hhi[(size_t)po * (B * H) + cidx] = hb;
        hlo[(size_t)po * (B * H) + cidx] = __float2bfloat16(hv - __bfloat162float(hb));
        if (s >= ctx)
            hs[((long)b * Sact + (s - ctx)) * H + n] = hv;

        // grid barrier: release h stores, arrive (RED), spin on acquire LOADS
        __threadfence();
        __syncthreads();
        if (t == 0) {
            atomicAdd(&g_arrive, 1u);
            const unsigned bound = (unsigned)NB * (unsigned)(s + 1);
            unsigned v;
            do {
                asm volatile("ld.acquire.gpu.global.u32 %0, [%1];"
                             : "=r"(v) : "l"(&g_arrive) : "memory");
            } while (v < bound);
        }
        __syncthreads();
    }
}

// ---------------------------------------------------------------------------
// Launch
// ---------------------------------------------------------------------------
extern "C" void kernel_launch(void* const* d_in, const int* in_sizes, int n_in,
                              void* d_out, int out_size)
{
    const int*   ids   = (const int*)  d_in[0];
    const float* emb   = (const float*)d_in[1];
    const float* w_ih  = (const float*)d_in[2];
    const float* w_hh  = (const float*)d_in[3];
    const float* b_ih  = (const float*)d_in[4];
    const float* b_hh  = (const float*)d_in[5];
    const float* w_out = (const float*)d_in[6];
    const float* b_out = (const float*)d_in[7];

    int ctx  = S - (int)((long)out_size / ((long)B * V));   // = 40
    int Sact = S - ctx;                                     // = 88

    float* xg;   cudaGetSymbolAddress((void**)&xg,   d_xg);
    float* hs;   cudaGetSymbolAddress((void**)&hs,   d_hs);
    int* rowids; cudaGetSymbolAddress((void**)&rowids, d_rowids);
    __nv_bfloat16* whi; cudaGetSymbolAddress((void**)&whi, d_whi);
    __nv_bfloat16* wlo; cudaGetSymbolAddress((void**)&wlo, d_wlo);
    __nv_bfloat16* hhi; cudaGetSymbolAddress((void**)&hhi, d_hhi);
    __nv_bfloat16* hlo; cudaGetSymbolAddress((void**)&hlo, d_hlo);

    static bool attr_set = false;
    if (!attr_set) {
        cudaFuncSetAttribute(lstm_scan, cudaFuncAttributeMaxDynamicSharedMemorySize,
                             SCAN_SMEM_BYTES);
        attr_set = true;
    }

    // 1) init h0 splits / barrier / gather ids; split w_hh into bf16 hi/lo
    init_kernel<<<(B * H + 255) / 256, 256>>>(ids, rowids, hhi, hlo);
    wsplit_kernel<<<(G * H + 255) / 256, 256>>>(w_hh, whi, wlo, G * H);

    // 2) x_gates = gather(emb, ids) @ w_ih^T + b_ih + b_hh   (tf32)
    gemm_tf32<<<dim3(G / 128, (S * B) / 128), 256>>>(
        emb, w_ih, b_ih, b_hh, xg, S * B, G, I_DIM, rowids);

    // 3) persistent scan: all 128 steps, W resident in SMEM
    lstm_scan<<<NB, 256, SCAN_SMEM_BYTES>>>(xg, whi, wlo, hhi, hlo, hs, ctx, Sact);

    // 4) logits = hs_flat @ w_out^T + b_out   (tf32)
    gemm_tf32<<<dim3(V / 128, (B * Sact) / 128), 256>>>(
        hs, w_out, b_out, nullptr, (float*)d_out, B * Sact, V, H, nullptr);
}

// round 9
// speedup vs baseline: 3.7807x; 1.0216x over previous
#include <cuda_runtime.h>
#include <cuda_bf16.h>
#include <math.h>

// Problem constants (fixed by setup_inputs)
#define B   32
#define S   128
#define I_DIM 1024
#define H   1024
#define G   4096      // 4*H
#define V   32000
#define NB  128       // scan grid (H/8), all co-resident (< 148 SMs, 1 blk/SM)

// ---------------------------------------------------------------------------
// Scratch (static __device__ arrays; no allocation allowed)
// ---------------------------------------------------------------------------
__device__ float d_xg[(size_t)S * B * G];             // precomputed input gates (S,B,4H)
__device__ float d_hs[(size_t)B * S * H];             // stored h, layout (b, s', H)
__device__ int   d_rowids[S * B];                     // gather indices for embed GEMM
__device__ __nv_bfloat16 d_whi[(size_t)G * H];        // w_hh hi split (bf16)
__device__ __nv_bfloat16 d_wlo[(size_t)G * H];        // w_hh lo split (bf16)
__device__ __nv_bfloat16 d_hhi[2][B * H];             // h hi split, ping-pong
__device__ __nv_bfloat16 d_hlo[2][B * H];             // h lo split, ping-pong
__device__ unsigned g_arrive;                         // grid-barrier arrival counter

// ---------------------------------------------------------------------------
// Init: zero h0 splits, reset barrier, build gather row ids.
// ---------------------------------------------------------------------------
__global__ void init_kernel(const int* __restrict__ ids, int* __restrict__ rowids,
                            __nv_bfloat16* __restrict__ hhi,
                            __nv_bfloat16* __restrict__ hlo)
{
    int t = blockIdx.x * blockDim.x + threadIdx.x;
    if (t == 0) g_arrive = 0u;
    if (t < S * B) {
        int s = t >> 5;
        int b = t & 31;
        rowids[t] = ids[b * S + s];
    }
    if (t < B * H) {
        hhi[t] = __float2bfloat16(0.f);
        hlo[t] = __float2bfloat16(0.f);
    }
}

// ---------------------------------------------------------------------------
// Split w_hh into bf16 hi/lo pair (hi + lo ~ fp32 to ~2^-17)
// ---------------------------------------------------------------------------
__global__ void wsplit_kernel(const float* __restrict__ w,
                              __nv_bfloat16* __restrict__ hi,
                              __nv_bfloat16* __restrict__ lo, int n)
{
    int i = blockIdx.x * blockDim.x + threadIdx.x;
    if (i < n) {
        float v = w[i];
        __nv_bfloat16 h = __float2bfloat16(v);
        hi[i] = h;
        lo[i] = __float2bfloat16(v - __bfloat162float(h));
    }
}

// ---------------------------------------------------------------------------
// mma / ldmatrix helpers
// ---------------------------------------------------------------------------
__device__ __forceinline__ unsigned f2tf(float f) {
    unsigned r;
    asm("cvt.rna.tf32.f32 %0, %1;" : "=r"(r) : "f"(f));
    return r;
}

#define MMA_TF32(d, a, b)                                                     \
    asm volatile(                                                             \
        "mma.sync.aligned.m16n8k8.row.col.f32.tf32.tf32.f32 "                 \
        "{%0,%1,%2,%3}, {%4,%5,%6,%7}, {%8,%9}, {%0,%1,%2,%3};\n"             \
        : "+f"(d[0]), "+f"(d[1]), "+f"(d[2]), "+f"(d[3])                      \
        : "r"(a[0]), "r"(a[1]), "r"(a[2]), "r"(a[3]), "r"(b[0]), "r"(b[1]))

#define MMA_BF16(d, a, b)                                                     \
    asm volatile(                                                             \
        "mma.sync.aligned.m16n8k16.row.col.f32.bf16.bf16.f32 "                \
        "{%0,%1,%2,%3}, {%4,%5,%6,%7}, {%8,%9}, {%0,%1,%2,%3};\n"             \
        : "+f"(d[0]), "+f"(d[1]), "+f"(d[2]), "+f"(d[3])                      \
        : "r"(a[0]), "r"(a[1]), "r"(a[2]), "r"(a[3]), "r"(b[0]), "r"(b[1]))

#define LDSM_X4(r, addr)                                                      \
    asm volatile("ldmatrix.sync.aligned.m8n8.x4.shared.b16 {%0,%1,%2,%3},[%4];" \
        : "=r"((r)[0]), "=r"((r)[1]), "=r"((r)[2]), "=r"((r)[3]) : "r"(addr))

#define LDSM_X2(r, addr)                                                      \
    asm volatile("ldmatrix.sync.aligned.m8n8.x2.shared.b16 {%0,%1},[%2];"     \
        : "=r"((r)[0]), "=r"((r)[1]) : "r"(addr))

// ---------------------------------------------------------------------------
// tf32 tensor-core GEMM (unchanged, known-good): C = A[row(m)] . Bm^T (+biases)
// ---------------------------------------------------------------------------
__global__ __launch_bounds__(256)
void gemm_tf32(const float* __restrict__ A, const float* __restrict__ Bm,
               const float* __restrict__ bias1, const float* __restrict__ bias2,
               float* __restrict__ C,
               int M, int N, int K,
               const int* __restrict__ arow)
{
    __shared__ unsigned As[128][20];
    __shared__ unsigned Bs[128][20];

    const int bm = blockIdx.y * 128;
    const int bn = blockIdx.x * 128;
    const int t    = threadIdx.x;
    const int lane = t & 31;
    const int w    = t >> 5;
    const int wm   = (w >> 2) * 64;
    const int wn   = (w & 3) * 32;
    const int gid  = lane >> 2;
    const int tk   = lane & 3;

    const int r0 = t >> 2;
    const int r1 = r0 + 64;
    const int kq = (t & 3) * 4;

    long ar0 = arow ? (long)arow[bm + r0] : (long)(bm + r0);
    long ar1 = arow ? (long)arow[bm + r1] : (long)(bm + r1);
    const float* Ap0 = A + ar0 * K + kq;
    const float* Ap1 = A + ar1 * K + kq;
    const float* Bp0 = Bm + (long)(bn + r0) * K + kq;
    const float* Bp1 = Bm + (long)(bn + r1) * K + kq;

    float acc[4][4][4];
    #pragma unroll
    for (int i = 0; i < 4; i++)
        #pragma unroll
        for (int j = 0; j < 4; j++)
            #pragma unroll
            for (int q = 0; q < 4; q++) acc[i][j][q] = 0.f;

    for (int k0 = 0; k0 < K; k0 += 16) {
        float4 va0 = *(const float4*)(Ap0 + k0);
        float4 va1 = *(const float4*)(Ap1 + k0);
        float4 vb0 = *(const float4*)(Bp0 + k0);
        float4 vb1 = *(const float4*)(Bp1 + k0);

        uint4 pa0 = make_uint4(f2tf(va0.x), f2tf(va0.y), f2tf(va0.z), f2tf(va0.w));
        uint4 pa1 = make_uint4(f2tf(va1.x), f2tf(va1.y), f2tf(va1.z), f2tf(va1.w));
        uint4 pb0 = make_uint4(f2tf(vb0.x), f2tf(vb0.y), f2tf(vb0.z), f2tf(vb0.w));
        uint4 pb1 = make_uint4(f2tf(vb1.x), f2tf(vb1.y), f2tf(vb1.z), f2tf(vb1.w));

        *(uint4*)&As[r0][kq] = pa0;
        *(uint4*)&As[r1][kq] = pa1;
        *(uint4*)&Bs[r0][kq] = pb0;
        *(uint4*)&Bs[r1][kq] = pb1;
        __syncthreads();

        #pragma unroll
        for (int ks = 0; ks < 16; ks += 8) {
            unsigned af[4][4], bf[4][2];
            #pragma unroll
            for (int i = 0; i < 4; i++) {
                int rb = wm + i * 16 + gid;
                af[i][0] = As[rb][ks + tk];
                af[i][1] = As[rb + 8][ks + tk];
                af[i][2] = As[rb][ks + tk + 4];
                af[i][3] = As[rb + 8][ks + tk + 4];
            }
            #pragma unroll
            for (int j = 0; j < 4; j++) {
                int nb = wn + j * 8 + gid;
                bf[j][0] = Bs[nb][ks + tk];
                bf[j][1] = Bs[nb][ks + tk + 4];
            }
            #pragma unroll
            for (int i = 0; i < 4; i++)
                #pragma unroll
                for (int j = 0; j < 4; j++)
                    MMA_TF32(acc[i][j], af[i], bf[j]);
        }
        __syncthreads();
    }

    #pragma unroll
    for (int i = 0; i < 4; i++) {
        int row = bm + wm + i * 16 + gid;
        #pragma unroll
        for (int j = 0; j < 4; j++) {
            int col = bn + wn + j * 8 + tk * 2;
            float b0v = 0.f, b1v = 0.f;
            if (bias1) { b0v += bias1[col]; b1v += bias1[col + 1]; }
            if (bias2) { b0v += bias2[col]; b1v += bias2[col + 1]; }
            float2 v0 = make_float2(acc[i][j][0] + b0v, acc[i][j][1] + b1v);
            float2 v1 = make_float2(acc[i][j][2] + b0v, acc[i][j][3] + b1v);
            *(float2*)&C[(long)row * N + col]       = v0;
            *(float2*)&C[(long)(row + 8) * N + col] = v1;
        }
    }
}

// ---------------------------------------------------------------------------
// Persistent tensor-core LSTM scan (all 128 steps, W resident in SMEM).
// R8: 4 independent accumulator chains (ILP across k-substeps) + ldmatrix
// frag loads (LDSM x4/x2 instead of 12 scalar LDS per k-substep).
// ---------------------------------------------------------------------------
#define KC 64
#define NCHUNK (H / KC)   // 16
#define WPITCH 36         // padded row pitch in 32-bit words (conflict-free)

#define SCAN_SMEM_BYTES ((2 * NCHUNK * 32 * WPITCH + 4 * 32 * WPITCH) * 4 + 4 * 32 * 8 * 4)

__global__ __launch_bounds__(256, 1)
void lstm_scan(const float* __restrict__ xg_base,
               const __nv_bfloat16* __restrict__ whi,
               const __nv_bfloat16* __restrict__ wlo,
               __nv_bfloat16* __restrict__ hhi,   // [2][B*H] ping-pong
               __nv_bfloat16* __restrict__ hlo,
               float* __restrict__ hs,
               int ctx, int Sact)
{
    extern __shared__ unsigned sm[];
    unsigned* wh  = sm;                            // [NCHUNK][32][WPITCH]
    unsigned* wl  = wh + NCHUNK * 32 * WPITCH;
    unsigned* shb = wl + NCHUNK * 32 * WPITCH;     // [2][32][WPITCH]
    unsigned* slb = shb + 2 * 32 * WPITCH;
    float* sgate  = (float*)(slb + 2 * 32 * WPITCH); // [4][32][8]

    const int t    = threadIdx.x;
    const int lane = t & 31;
    const int w    = t >> 5;
    const int wm   = (w >> 2) * 16;   // m-half base (0 or 16)
    const int g    = w & 3;           // gate
    const int gid  = lane >> 2;
    const int tk   = lane & 3;
    const int n0   = blockIdx.x * 8;

    // staging mapping: 256 threads = 32 rows x 8 uint4 (8 bf16) chunks
    const int sr   = t >> 3;
    const int sq   = (t & 7) * 4;
    const int wrow = (sr >> 3) * H + n0 + (sr & 7);

    // --- load this block's W slice into persistent smem (once) ---
    const uint4* gWhi = (const uint4*)(whi + (long)wrow * H) + (t & 7);
    const uint4* gWlo = (const uint4*)(wlo + (long)wrow * H) + (t & 7);
    #pragma unroll 4
    for (int ch = 0; ch < NCHUNK; ch++) {
        *(uint4*)&wh[(ch * 32 + sr) * WPITCH + sq] = gWhi[ch * 8];
        *(uint4*)&wl[(ch * 32 + sr) * WPITCH + sq] = gWlo[ch * 8];
    }

    // ldmatrix lane->address mapping (byte offsets into a 32xWPITCH tile)
    // A (x4): row = wm + (lane&7) + ((lane>>3)&1)*8, k-half = lane>>4
    // B (x2): row = g*8 + (lane&7),                  k-half = (lane>>3)&1
    const int a_row = wm + (lane & 7) + ((lane >> 3) & 1) * 8;
    const int a_kh  = (lane >> 4) * 4;                 // word offset
    const unsigned a_off = (unsigned)(a_row * WPITCH + a_kh) * 4;
    const int b_row = g * 8 + (lane & 7);
    const int b_kh  = ((lane >> 3) & 1) * 4;
    const unsigned b_off = (unsigned)(b_row * WPITCH + b_kh) * 4;

    const unsigned shb_base = (unsigned)__cvta_generic_to_shared(shb);
    const unsigned slb_base = (unsigned)__cvta_generic_to_shared(slb);
    const unsigned wh_base  = (unsigned)__cvta_generic_to_shared(wh);
    const unsigned wl_base  = (unsigned)__cvta_generic_to_shared(wl);
    const unsigned TILE_B   = 32 * WPITCH * 4;         // bytes per 32-row tile

    const int b = t & 31;
    const int j = t >> 5;
    const int n = n0 + j;
    float cval  = 0.f;
    const float* xgp = xg_base + b * G + n;

    __syncthreads();

    for (int s = 0; s < S; s++) {
        const int pi = s & 1;
        const uint4* gHhi = (const uint4*)(hhi + (size_t)pi * (B * H) + sr * H) + (t & 7);
        const uint4* gHlo = (const uint4*)(hlo + (size_t)pi * (B * H) + sr * H) + (t & 7);

        // hoisted xg loads — independent of h, hidden behind chunk loop
        const float* xgs = xgp + (size_t)s * (B * G);
        float xgi = __ldg(xgs);
        float xgf = __ldg(xgs + H);
        float xgg = __ldg(xgs + 2 * H);
        float xgo = __ldg(xgs + 3 * H);

        // prefetch chunks 0 and 1 (distance 2)
        uint4 rh[2], rl[2];
        rh[0] = __ldcg(gHhi);     rl[0] = __ldcg(gHlo);
        rh[1] = __ldcg(gHhi + 8); rl[1] = __ldcg(gHlo + 8);

        // 4 independent accumulator chains (one per 16-k substep)
        float acc[4][4];
        #pragma unroll
        for (int q = 0; q < 4; q++)
            #pragma unroll
            for (int e = 0; e < 4; e++) acc[q][e] = 0.f;

        #pragma unroll
        for (int ch = 0; ch < NCHUNK; ch++) {
            const int buf = ch & 1;
            unsigned* sh = shb + buf * 32 * WPITCH;
            unsigned* sl = slb + buf * 32 * WPITCH;
            *(uint4*)&sh[sr * WPITCH + sq] = rh[buf];
            *(uint4*)&sl[sr * WPITCH + sq] = rl[buf];
            __syncthreads();

            if (ch + 2 < NCHUNK) {            // prefetch 2 chunks ahead
                rh[buf] = __ldcg(gHhi + (ch + 2) * 8);
                rl[buf] = __ldcg(gHlo + (ch + 2) * 8);
            }

            const unsigned sha = shb_base + buf * TILE_B + a_off;
            const unsigned sla = slb_base + buf * TILE_B + a_off;
            const unsigned whb = wh_base  + ch  * TILE_B + b_off;
            const unsigned wlb = wl_base  + ch  * TILE_B + b_off;

            unsigned Ahi[4][4], Alo[4][4], Bhi[4][2], Blo[4][2];
            #pragma unroll
            for (int ks = 0; ks < 4; ks++) {
                LDSM_X4(Ahi[ks], sha + ks * 32);   // kb = 8 words = 32 bytes
                LDSM_X4(Alo[ks], sla + ks * 32);
                LDSM_X2(Bhi[ks], whb + ks * 32);
                LDSM_X2(Blo[ks], wlb + ks * 32);
            }
            // term-major order: dependency distance = 4 per acc chain
            #pragma unroll
            for (int ks = 0; ks < 4; ks++) MMA_BF16(acc[ks], Ahi[ks], Bhi[ks]);
            #pragma unroll
            for (int ks = 0; ks < 4; ks++) MMA_BF16(acc[ks], Alo[ks], Bhi[ks]);
            #pragma unroll
            for (int ks = 0; ks < 4; ks++) MMA_BF16(acc[ks], Ahi[ks], Blo[ks]);
        }

        // reduce the 4 chains
        float fin[4];
        #pragma unroll
        for (int e = 0; e < 4; e++)
            fin[e] = (acc[0][e] + acc[1][e]) + (acc[2][e] + acc[3][e]);

        // gate exchange
        __syncthreads();
        sgate[(g * 32 + wm + gid) * 8 + 2 * tk]         = fin[0];
        sgate[(g * 32 + wm + gid) * 8 + 2 * tk + 1]     = fin[1];
        sgate[(g * 32 + wm + gid + 8) * 8 + 2 * tk]     = fin[2];
        sgate[(g * 32 + wm + gid + 8) * 8 + 2 * tk + 1] = fin[3];
        __syncthreads();

        // fused pointwise: thread = (b, j)
        float gi = sgate[(0 * 32 + b) * 8 + j] + xgi;
        float gf = sgate[(1 * 32 + b) * 8 + j] + xgf;
        float gg = sgate[(2 * 32 + b) * 8 + j] + xgg;
        float go = sgate[(3 * 32 + b) * 8 + j] + xgo;

        float iv = 1.f / (1.f + __expf(-gi));
        float fv = 1.f / (1.f + __expf(-gf));
        float gv = tanhf(gg);
        float ov = 1.f / (1.f + __expf(-go));

        cval = fv * cval + iv * gv;
        float hv = ov * tanhf(cval);

        const int po = (s + 1) & 1;
        const int cidx = b * H + n;
        __nv_bfloat16 hb = __float2bfloat16(hv);
        hhi[(size_t)po * (B * H) + cidx] = hb;
        hlo[(size_t)po * (B * H) + cidx] = __float2bfloat16(hv - __bfloat162float(hb));
        if (s >= ctx)
            hs[((long)b * Sact + (s - ctx)) * H + n] = hv;

        // grid barrier: release h stores, arrive (RED), spin on acquire LOADS
        __threadfence();
        __syncthreads();
        if (t == 0) {
            atomicAdd(&g_arrive, 1u);
            const unsigned bound = (unsigned)NB * (unsigned)(s + 1);
            unsigned v;
            do {
                asm volatile("ld.acquire.gpu.global.u32 %0, [%1];"
                             : "=r"(v) : "l"(&g_arrive) : "memory");
            } while (v < bound);
        }
        __syncthreads();
    }
}

// ---------------------------------------------------------------------------
// Launch
// ---------------------------------------------------------------------------
extern "C" void kernel_launch(void* const* d_in, const int* in_sizes, int n_in,
                              void* d_out, int out_size)
{
    const int*   ids   = (const int*)  d_in[0];
    const float* emb   = (const float*)d_in[1];
    const float* w_ih  = (const float*)d_in[2];
    const float* w_hh  = (const float*)d_in[3];
    const float* b_ih  = (const float*)d_in[4];
    const float* b_hh  = (const float*)d_in[5];
    const float* w_out = (const float*)d_in[6];
    const float* b_out = (const float*)d_in[7];

    int ctx  = S - (int)((long)out_size / ((long)B * V));   // = 40
    int Sact = S - ctx;                                     // = 88

    float* xg;   cudaGetSymbolAddress((void**)&xg,   d_xg);
    float* hs;   cudaGetSymbolAddress((void**)&hs,   d_hs);
    int* rowids; cudaGetSymbolAddress((void**)&rowids, d_rowids);
    __nv_bfloat16* whi; cudaGetSymbolAddress((void**)&whi, d_whi);
    __nv_bfloat16* wlo; cudaGetSymbolAddress((void**)&wlo, d_wlo);
    __nv_bfloat16* hhi; cudaGetSymbolAddress((void**)&hhi, d_hhi);
    __nv_bfloat16* hlo; cudaGetSymbolAddress((void**)&hlo, d_hlo);

    static bool attr_set = false;
    if (!attr_set) {
        cudaFuncSetAttribute(lstm_scan, cudaFuncAttributeMaxDynamicSharedMemorySize,
                             SCAN_SMEM_BYTES);
        attr_set = true;
    }

    // 1) init h0 splits / barrier / gather ids; split w_hh into bf16 hi/lo
    init_kernel<<<(B * H + 255) / 256, 256>>>(ids, rowids, hhi, hlo);
    wsplit_kernel<<<(G * H + 255) / 256, 256>>>(w_hh, whi, wlo, G * H);

    // 2) x_gates = gather(emb, ids) @ w_ih^T + b_ih + b_hh   (tf32)
    gemm_tf32<<<dim3(G / 128, (S * B) / 128), 256>>>(
        emb, w_ih, b_ih, b_hh, xg, S * B, G, I_DIM, rowids);

    // 3) persistent scan: all 128 steps, W resident in SMEM
    lstm_scan<<<NB, 256, SCAN_SMEM_BYTES>>>(xg, whi, wlo, hhi, hlo, hs, ctx, Sact);

    // 4) logits = hs_flat @ w_out^T + b_out   (tf32)
    gemm_tf32<<<dim3(V / 128, (B * Sact) / 128), 256>>>(
        hs, w_out, b_out, nullptr, (float*)d_out, B * Sact, V, H, nullptr);
}